// round 8
// baseline (speedup 1.0000x reference)
#include <cuda_runtime.h>
#include <cuda_fp16.h>
#include <cstdint>

// Problem: B=16384, D=1024, T=512
// out[b,t] = (x@Wb + bb) + cumsum_t( relu(x@Wh^T + bh) )
// Single-pass FP16 HMMA. X is converted fp32->fp16 INSIDE the mainloop during
// nc=0 (and cached to g_xh for nc=1); base dot-product folded into the convert.
// 4-stage cp.async pipeline, flat 64-chunk loop, separate hazard buffer so the
// nc-boundary epilogue overlaps with prefetch. Split (2 threads/row) scan.

#define D_DIM 1024
#define T_DIM 512
#define BM    128
#define BN    256
#define BK    32
#define THREADS 256
#define HPITCH 132            // hazard row pitch (floats) for a 128-col half

// ---- global scratch ----
__device__ __half g_xh[16384 * D_DIM];
__device__ __half g_wh[T_DIM * D_DIM];

// ---- smem layout (bytes) ----
#define SM_BH    0                       // 512 f   (2048)
#define SM_WB    2048                    // 1024 f  (4096)
#define SM_CARRY 6144                    // 128 f   (512)
#define SM_RED   6656                    // 256 f   (1024)
#define SM_STOT0 7680                    // 128 f
#define SM_STOT1 8192                    // 128 f
#define SM_CONV  8704                    // 8192 (A fp16 conv buffer, 512B-aligned)
#define SM_ASTG  16896                   // 4 stages x 16384 (fp32 nc0 / fp16 nc1)
#define SM_BSTG  82432                   // 4 stages x 16384
#define SM_HAZ   147968                  // 128*HPITCH*4 = 67584
#define SMEM_TOTAL 215552

// ---------------- helpers ----------------
__device__ __forceinline__ uint32_t smem_u32(const void* p) {
    uint32_t a;
    asm("{ .reg .u64 t; cvta.to.shared.u64 t, %1; cvt.u32.u64 %0, t; }" : "=r"(a) : "l"(p));
    return a;
}
__device__ __forceinline__ uint32_t swz64(uint32_t o) { return o ^ ((o >> 3) & 0x30); }

#define CP16(dst, src) \
    asm volatile("cp.async.cg.shared.global [%0], [%1], 16;" :: "r"(dst), "l"(src) : "memory")
#define CP_COMMIT() asm volatile("cp.async.commit_group;" ::: "memory")
#define CP_WAIT0()  asm volatile("cp.async.wait_group 0;" ::: "memory")
#define CP_WAIT1()  asm volatile("cp.async.wait_group 1;" ::: "memory")
#define CP_WAIT2()  asm volatile("cp.async.wait_group 2;" ::: "memory")

__device__ __forceinline__ void ldsm4(uint32_t* r, uint32_t addr) {
    asm volatile("ldmatrix.sync.aligned.m8n8.x4.shared.b16 {%0,%1,%2,%3}, [%4];"
                 : "=r"(r[0]), "=r"(r[1]), "=r"(r[2]), "=r"(r[3]) : "r"(addr));
}
__device__ __forceinline__ void mma16816(float* d, const uint32_t* a, const uint32_t* b) {
    asm volatile(
        "mma.sync.aligned.m16n8k16.row.col.f32.f16.f16.f32 "
        "{%0,%1,%2,%3}, {%4,%5,%6,%7}, {%8,%9}, {%0,%1,%2,%3};"
        : "+f"(d[0]), "+f"(d[1]), "+f"(d[2]), "+f"(d[3])
        : "r"(a[0]), "r"(a[1]), "r"(a[2]), "r"(a[3]), "r"(b[0]), "r"(b[1]));
}
__device__ __forceinline__ uint32_t pk2h(float a, float b) {
    __half2 h = __floats2half2_rn(a, b);
    return *(uint32_t*)&h;
}

// -------- prologue: convert Wh to fp16 --------
__global__ __launch_bounds__(256)
void wh_conv_kernel(const float* __restrict__ Wh) {
    int i = (blockIdx.x * 256 + threadIdx.x) * 4;
    float4 w = *(const float4*)(Wh + i);
    uint2 v = { pk2h(w.x, w.y), pk2h(w.z, w.w) };
    *(uint2*)((char*)g_wh + (size_t)i * 2) = v;
}

// -------- main fused kernel --------
__global__ __launch_bounds__(THREADS, 1)
void fused_kernel(const float* __restrict__ X,
                  const float* __restrict__ bh,
                  const float* __restrict__ Wb,
                  const float* __restrict__ bb,
                  float* __restrict__ out) {
    extern __shared__ char sm[];
    const uint32_t su = smem_u32(sm);
    const int tid = threadIdx.x;
    const int lane = tid & 31;
    const int wid = tid >> 5;
    const int warprow = wid >> 2;   // 0..1 -> m *64
    const int warpcol = wid & 3;    // 0..3 -> n *64
    const int bm = blockIdx.x * BM;

    float* sbh = (float*)(sm + SM_BH);
    float* swb = (float*)(sm + SM_WB);
    float* scarry = (float*)(sm + SM_CARRY);
    float* sred = (float*)(sm + SM_RED);
    float* stot0 = (float*)(sm + SM_STOT0);
    float* stot1 = (float*)(sm + SM_STOT1);
    float* shz = (float*)(sm + SM_HAZ);       // [128][HPITCH]

    for (int i = tid; i < T_DIM; i += THREADS) sbh[i] = bh[i];
    for (int i = tid; i < D_DIM; i += THREADS) swb[i] = Wb[i];
    __syncthreads();

    // ldsm fragment address components
    const uint32_t a_rowoff = (uint32_t)(warprow * 64 + (lane & 15)) * 64;
    const uint32_t a_l16 = ((lane >> 4) & 1) * 16;
    const uint32_t b_rowoff = (uint32_t)(warpcol * 64 + (lane & 7) + ((lane >> 4) & 1) * 8) * 64;
    const uint32_t b_l16 = ((lane >> 3) & 1) * 16;
    const uint32_t xmask = (uint32_t)(lane & 6) << 3;

    // A16 cp.async mapping (nc=1): 512 segs, 2/thread
    const int aseg = tid * 2;
    const int arow0 = aseg >> 2, ac0 = aseg & 3;
    const int arow1 = (aseg + 1) >> 2, ac1 = (aseg + 1) & 3;

    // convert mapping (nc=0): row r, half h (16 floats each)
    const int cvr = tid >> 1;
    const int cvh = tid & 1;

    float pbase = 0.0f;
    float acc[128];
#pragma unroll
    for (int j = 0; j < 128; j++) acc[j] = 0.0f;

#pragma unroll 1
    for (int i = 0; i < 66; i++) {
        // ---- issue loads for chunk i into stage i%4 ----
        if (i < 64) {
            const int nci = i >> 5;
            const int k0 = (i & 31) * BK;
            const uint32_t sA = su + SM_ASTG + (i & 3) * 16384;
            const uint32_t sB = su + SM_BSTG + (i & 3) * 16384;
            if (nci == 0) {
                // A fp32: 128 rows x 128B, 1024 segs, 4/thread, linear layout
#pragma unroll
                for (int q = 0; q < 4; q++) {
                    int seg = tid * 4 + q;
                    int row = seg >> 3, c8 = seg & 7;
                    const char* gp = (const char*)(X + (size_t)(bm + row) * D_DIM + k0) + c8 * 16;
                    CP16(sA + row * 128 + c8 * 16, gp);
                }
            } else {
                // A fp16 from g_xh: 512 segs, 2/thread, swizzled
                size_t gb0 = ((size_t)(bm + arow0) * D_DIM + k0) * 2 + ac0 * 16;
                size_t gb1 = ((size_t)(bm + arow1) * D_DIM + k0) * 2 + ac1 * 16;
                CP16(sA + swz64((uint32_t)(arow0 * 64 + ac0 * 16)), (const char*)g_xh + gb0);
                CP16(sA + swz64((uint32_t)(arow1 * 64 + ac1 * 16)), (const char*)g_xh + gb1);
            }
            // B: 256 rows of Wh, 1024 segs, 4/thread, swizzled
#pragma unroll
            for (int q = 0; q < 4; q++) {
                int seg = tid * 4 + q;
                int row = seg >> 2, c = seg & 3;
                size_t gb = ((size_t)(nci * BN + row) * D_DIM + k0) * 2 + c * 16;
                CP16(sB + swz64((uint32_t)(row * 64 + c * 16)), (const char*)g_wh + gb);
            }
            CP_COMMIT();
        }
        if (i < 2) continue;

        const int c = i - 2;                  // chunk being computed
        if (i < 64) CP_WAIT2();
        else if (i == 64) CP_WAIT1();
        else CP_WAIT0();
        __syncthreads();

        const uint32_t sA = su + SM_ASTG + (c & 3) * 16384;
        const uint32_t sB = su + SM_BSTG + (c & 3) * 16384;
        uint32_t aBase;

        if (c < 32) {
            // ---- convert A fp32 -> fp16 conv buffer (+STG g_xh, +base dot) ----
            const int k0c = c * BK;
            const float* src = (const float*)(sm + SM_ASTG + (c & 3) * 16384) + cvr * 32 + cvh * 16;
            float v[16];
            *(float4*)(v + 0)  = *(const float4*)(src + 0);
            *(float4*)(v + 4)  = *(const float4*)(src + 4);
            *(float4*)(v + 8)  = *(const float4*)(src + 8);
            *(float4*)(v + 12) = *(const float4*)(src + 12);
            const float* wbp = swb + k0c + cvh * 16;
#pragma unroll
            for (int j = 0; j < 16; j++) pbase = fmaf(v[j], wbp[j], pbase);
            uint4 h0 = { pk2h(v[0], v[1]),  pk2h(v[2], v[3]),
                         pk2h(v[4], v[5]),  pk2h(v[6], v[7]) };
            uint4 h1 = { pk2h(v[8], v[9]),  pk2h(v[10], v[11]),
                         pk2h(v[12], v[13]), pk2h(v[14], v[15]) };
            uint32_t rb = (uint32_t)cvr * 64 + cvh * 32;
            *(uint4*)(sm + SM_CONV + swz64(rb))      = h0;
            *(uint4*)(sm + SM_CONV + swz64(rb + 16)) = h1;
            char* gx = (char*)g_xh + ((size_t)(bm + cvr) * D_DIM + k0c + cvh * 16) * 2;
            *(uint4*)(gx)      = h0;
            *(uint4*)(gx + 16) = h1;
            __syncthreads();
            aBase = su + SM_CONV;
        } else {
            aBase = sA;
        }

        // ---- compute chunk c ----
#pragma unroll
        for (int kk = 0; kk < 2; kk++) {
            const uint32_t akb = (kk * 32 + a_l16) ^ xmask;
            const uint32_t bkb = (kk * 32 + b_l16) ^ xmask;
            uint32_t bfr[4][4];
#pragma unroll
            for (int p = 0; p < 4; p++)
                ldsm4(bfr[p], sB + b_rowoff + p * 16 * 64 + bkb);
#pragma unroll
            for (int mt = 0; mt < 4; mt++) {
                uint32_t af[4];
                ldsm4(af, aBase + a_rowoff + mt * 16 * 64 + akb);
#pragma unroll
                for (int nt = 0; nt < 8; nt++) {
                    float* d = acc + (mt * 8 + nt) * 4;
                    mma16816(d, af, &bfr[nt >> 1][(nt & 1) * 2]);
                }
            }
        }

        // ---- nc boundary: epilogue ----
        if (c == 31 || c == 63) {
            const int nc = c >> 5;
            __syncthreads();
            if (nc == 0) {
                // base reduction -> carry init
                sred[tid] = pbase;
                __syncthreads();
                if (tid < BM) scarry[tid] = sred[2 * tid] + sred[2 * tid + 1] + bb[0];
                __syncthreads();
            }
#pragma unroll 1
            for (int half = 0; half < 2; half++) {
                // write hazards for this 128-col half
                if ((warpcol >> 1) == half) {
#pragma unroll
                    for (int mt = 0; mt < 4; mt++)
#pragma unroll
                        for (int nt = 0; nt < 8; nt++) {
                            const float* d = acc + (mt * 8 + nt) * 4;
                            int r0 = warprow * 64 + mt * 16 + (lane >> 2);
                            int c0 = (warpcol & 1) * 64 + nt * 8 + 2 * (lane & 3);
                            int cg = nc * BN + half * 128 + c0;
                            float b0 = sbh[cg], b1 = sbh[cg + 1];
                            shz[r0 * HPITCH + c0]           = fmaxf(d[0] + b0, 0.0f);
                            shz[r0 * HPITCH + c0 + 1]       = fmaxf(d[1] + b1, 0.0f);
                            shz[(r0 + 8) * HPITCH + c0]     = fmaxf(d[2] + b0, 0.0f);
                            shz[(r0 + 8) * HPITCH + c0 + 1] = fmaxf(d[3] + b1, 0.0f);
                        }
                }
                __syncthreads();
                // split scan: 2 threads/row, 64 cols each
                {
                    int r = tid >> 1, hh = tid & 1;
                    float run = 0.0f;
                    float4* rp = (float4*)(shz + r * HPITCH + hh * 64);
#pragma unroll 4
                    for (int j = 0; j < 16; j++) {
                        float4 v4 = rp[j];
                        v4.x += run; v4.y += v4.x; v4.z += v4.y; v4.w += v4.z;
                        run = v4.w;
                        rp[j] = v4;
                    }
                    if (hh == 0) stot0[r] = run; else stot1[r] = run;
                }
                __syncthreads();
                // coalesced store (+carry, +half fixup)
#pragma unroll
                for (int it = 0; it < 16; it++) {
                    int idx = it * 256 + tid;          // 4096 float4
                    int row = idx >> 5;
                    int c4 = (idx & 31) * 4;
                    float add = scarry[row] + (c4 >= 64 ? stot0[row] : 0.0f);
                    const float* rp = shz + row * HPITCH + c4;
                    float4 o = { rp[0] + add, rp[1] + add, rp[2] + add, rp[3] + add };
                    *(float4*)(out + (size_t)(bm + row) * T_DIM + nc * BN + half * 128 + c4) = o;
                }
                __syncthreads();
                if (tid < BM) scarry[tid] += stot0[tid] + stot1[tid];
                __syncthreads();
            }
            if (nc == 0) {
#pragma unroll
                for (int j = 0; j < 128; j++) acc[j] = 0.0f;
            }
        }
    }
}

extern "C" void kernel_launch(void* const* d_in, const int* in_sizes, int n_in,
                              void* d_out, int out_size) {
    const float* x  = (const float*)d_in[0];
    const float* Wh = (const float*)d_in[1];
    const float* bh = (const float*)d_in[2];
    const float* Wb = (const float*)d_in[3];
    const float* bb = (const float*)d_in[4];
    float* out = (float*)d_out;

    const int B = in_sizes[0] / D_DIM;   // 16384

    cudaFuncSetAttribute(fused_kernel,
                         cudaFuncAttributeMaxDynamicSharedMemorySize, SMEM_TOTAL);

    wh_conv_kernel<<<(T_DIM * D_DIM) / 1024, 256>>>(Wh);
    fused_kernel<<<B / BM, THREADS, SMEM_TOTAL>>>(x, bh, Wb, bb, out);
}

// round 9
// speedup vs baseline: 1.2253x; 1.2253x over previous
#include <cuda_runtime.h>
#include <cuda_fp16.h>
#include <cstdint>

// Problem: B=16384, D=1024, T=512
// out[b,t] = (x@Wb + bb) + cumsum_t( relu(x@Wh^T + bh) )
// Single-pass FP16 HMMA. 512 threads / 16 warps, warp tile 32x64 (acc=64 regs,
// no spills; r7 post-mortem: 64x64 tiles -> 255 regs -> spill-bound). Separate
// x-conversion prologue. 4-stage cp.async pipeline; hazard buffer separate
// from stages so the nc-boundary epilogue overlaps prefetch.

#define D_DIM 1024
#define T_DIM 512
#define BM    128
#define BN    256
#define BK    32
#define THREADS 512
#define HPITCH 132            // floats, per 128-col half

// ---- global scratch ----
__device__ __half g_xh[16384 * D_DIM];
__device__ __half g_wh[T_DIM * D_DIM];
__device__ float g_base[16384];

// ---- smem layout (bytes) ----
#define SM_BH    0                       // 512 f (2048)
#define SM_CARRY 2048                    // 128 f (512)
#define SM_STOT  2560                    // 4*128 f (2048)
#define SM_PREF  4608                    // 512 f (2048)
#define SM_ASTG  6656                    // 4 x 8192
#define SM_BSTG  39424                   // 4 x 16384
#define SM_HAZ   104960                  // 128*132*4 = 67584
#define SMEM_TOTAL 172544

// ---------------- helpers ----------------
__device__ __forceinline__ uint32_t smem_u32(const void* p) {
    uint32_t a;
    asm("{ .reg .u64 t; cvta.to.shared.u64 t, %1; cvt.u32.u64 %0, t; }" : "=r"(a) : "l"(p));
    return a;
}
__device__ __forceinline__ uint32_t swz64(uint32_t o) { return o ^ ((o >> 3) & 0x30); }

#define CP16(dst, src) \
    asm volatile("cp.async.cg.shared.global [%0], [%1], 16;" :: "r"(dst), "l"(src) : "memory")
#define CP_COMMIT() asm volatile("cp.async.commit_group;" ::: "memory")
#define CP_WAIT0()  asm volatile("cp.async.wait_group 0;" ::: "memory")
#define CP_WAIT1()  asm volatile("cp.async.wait_group 1;" ::: "memory")
#define CP_WAIT2()  asm volatile("cp.async.wait_group 2;" ::: "memory")

__device__ __forceinline__ void ldsm4(uint32_t* r, uint32_t addr) {
    asm volatile("ldmatrix.sync.aligned.m8n8.x4.shared.b16 {%0,%1,%2,%3}, [%4];"
                 : "=r"(r[0]), "=r"(r[1]), "=r"(r[2]), "=r"(r[3]) : "r"(addr));
}
__device__ __forceinline__ void mma16816(float* d, const uint32_t* a, const uint32_t* b) {
    asm volatile(
        "mma.sync.aligned.m16n8k16.row.col.f32.f16.f16.f32 "
        "{%0,%1,%2,%3}, {%4,%5,%6,%7}, {%8,%9}, {%0,%1,%2,%3};"
        : "+f"(d[0]), "+f"(d[1]), "+f"(d[2]), "+f"(d[3])
        : "r"(a[0]), "r"(a[1]), "r"(a[2]), "r"(a[3]), "r"(b[0]), "r"(b[1]));
}
__device__ __forceinline__ uint32_t pk2h(float a, float b) {
    __half2 h = __floats2half2_rn(a, b);
    return *(uint32_t*)&h;
}

// -------- prologue 1: convert Wh to fp16 --------
__global__ __launch_bounds__(256)
void wh_conv_kernel(const float* __restrict__ Wh) {
    int i = (blockIdx.x * 256 + threadIdx.x) * 4;
    float4 w = *(const float4*)(Wh + i);
    uint2 v = { pk2h(w.x, w.y), pk2h(w.z, w.w) };
    *(uint2*)((char*)g_wh + (size_t)i * 2) = v;
}

// -------- prologue 2: convert X + per-row base = x@Wb + bb --------
__global__ __launch_bounds__(256)
void x_conv_base_kernel(const float* __restrict__ X,
                        const float* __restrict__ Wb,
                        const float* __restrict__ bb) {
    __shared__ float red[8];
    const int row = blockIdx.x;
    const int tid = threadIdx.x;
    const int c = tid * 4;

    float4 xv = *(const float4*)(X + (size_t)row * D_DIM + c);
    float4 wv = *(const float4*)(Wb + c);

    float p = xv.x * wv.x + xv.y * wv.y + xv.z * wv.z + xv.w * wv.w;
    uint2 vh = { pk2h(xv.x, xv.y), pk2h(xv.z, xv.w) };
    *(uint2*)((char*)g_xh + ((size_t)row * D_DIM + c) * 2) = vh;

#pragma unroll
    for (int o = 16; o > 0; o >>= 1) p += __shfl_down_sync(0xffffffffu, p, o);
    if ((tid & 31) == 0) red[tid >> 5] = p;
    __syncthreads();
    if (tid == 0) {
        float s = 0.0f;
#pragma unroll
        for (int j = 0; j < 8; j++) s += red[j];
        g_base[row] = s + bb[0];
    }
}

// -------- main fused GEMM + scan kernel --------
__global__ __launch_bounds__(THREADS, 1)
void fused_kernel(const float* __restrict__ bh,
                  float* __restrict__ out) {
    extern __shared__ char sm[];
    const uint32_t su = smem_u32(sm);
    const int tid = threadIdx.x;
    const int lane = tid & 31;
    const int wid = tid >> 5;
    const int warprow = wid >> 2;   // 0..3 -> m *32
    const int warpcol = wid & 3;    // 0..3 -> n *64
    const int bm = blockIdx.x * BM;

    float* sbh = (float*)(sm + SM_BH);
    float* scarry = (float*)(sm + SM_CARRY);
    float* stot = (float*)(sm + SM_STOT);     // [4][128]
    float* spref = (float*)(sm + SM_PREF);    // [128][4]
    float* shz = (float*)(sm + SM_HAZ);       // [128][HPITCH]

    for (int i = tid; i < T_DIM; i += THREADS) sbh[i] = bh[i];
    if (tid < BM) scarry[tid] = g_base[bm + tid];
    __syncthreads();

    // ldsm fragment address components
    const uint32_t a_rowoff = (uint32_t)(warprow * 32 + (lane & 15)) * 64;
    const uint32_t a_l16 = ((lane >> 4) & 1) * 16;
    const uint32_t b_rowoff = (uint32_t)(warpcol * 64 + (lane & 7) + ((lane >> 4) & 1) * 8) * 64;
    const uint32_t b_l16 = ((lane >> 3) & 1) * 16;
    const uint32_t xmask = (uint32_t)(lane & 6) << 3;

    // cp.async mapping: A 512 segs (1/thread), B 1024 segs (2/thread)
    const int arow = tid >> 2, ac = tid & 3;
    const uint32_t adst = swz64((uint32_t)(arow * 64 + ac * 16));

    float acc[64];
#pragma unroll
    for (int j = 0; j < 64; j++) acc[j] = 0.0f;

#pragma unroll 1
    for (int i = 0; i < 66; i++) {
        // ---- issue loads for chunk i into stage i%4 ----
        if (i < 64) {
            const int nci = i >> 5;
            const int k0 = (i & 31) * BK;
            const uint32_t sA = su + SM_ASTG + (i & 3) * 8192;
            const uint32_t sB = su + SM_BSTG + (i & 3) * 16384;
            // A: 128 rows fp16
            CP16(sA + adst,
                 (const char*)g_xh + ((size_t)(bm + arow) * D_DIM + k0) * 2 + ac * 16);
            // B: 256 rows of Wh
#pragma unroll
            for (int q = 0; q < 2; q++) {
                int seg = tid * 2 + q;
                int row = seg >> 2, c = seg & 3;
                size_t gb = ((size_t)(nci * BN + row) * D_DIM + k0) * 2 + c * 16;
                CP16(sB + swz64((uint32_t)(row * 64 + c * 16)), (const char*)g_wh + gb);
            }
            CP_COMMIT();
        }
        if (i < 2) continue;

        const int c = i - 2;
        if (i < 64) CP_WAIT2();
        else if (i == 64) CP_WAIT1();
        else CP_WAIT0();
        __syncthreads();

        const uint32_t sA = su + SM_ASTG + (c & 3) * 8192;
        const uint32_t sB = su + SM_BSTG + (c & 3) * 16384;

        // ---- compute chunk c ----
#pragma unroll
        for (int kk = 0; kk < 2; kk++) {
            const uint32_t akb = (kk * 32 + a_l16) ^ xmask;
            const uint32_t bkb = (kk * 32 + b_l16) ^ xmask;
            uint32_t bfr[4][4];
#pragma unroll
            for (int p = 0; p < 4; p++)
                ldsm4(bfr[p], sB + b_rowoff + p * 16 * 64 + bkb);
#pragma unroll
            for (int mt = 0; mt < 2; mt++) {
                uint32_t af[4];
                ldsm4(af, sA + a_rowoff + mt * 16 * 64 + akb);
#pragma unroll
                for (int nt = 0; nt < 8; nt++) {
                    float* d = acc + (mt * 8 + nt) * 4;
                    mma16816(d, af, &bfr[nt >> 1][(nt & 1) * 2]);
                }
            }
        }

        // ---- nc boundary: epilogue (stages keep prefetching underneath) ----
        if (c == 31 || c == 63) {
            const int nc = c >> 5;
#pragma unroll 1
            for (int half = 0; half < 2; half++) {
                __syncthreads();
                // write hazards for this 128-col half
                if ((warpcol >> 1) == half) {
#pragma unroll
                    for (int mt = 0; mt < 2; mt++)
#pragma unroll
                        for (int nt = 0; nt < 8; nt++) {
                            const float* d = acc + (mt * 8 + nt) * 4;
                            int r0 = warprow * 32 + mt * 16 + (lane >> 2);
                            int c0 = (warpcol & 1) * 64 + nt * 8 + 2 * (lane & 3);
                            int cg = nc * BN + half * 128 + c0;
                            float b0 = sbh[cg], b1 = sbh[cg + 1];
                            shz[r0 * HPITCH + c0]           = fmaxf(d[0] + b0, 0.0f);
                            shz[r0 * HPITCH + c0 + 1]       = fmaxf(d[1] + b1, 0.0f);
                            shz[(r0 + 8) * HPITCH + c0]     = fmaxf(d[2] + b0, 0.0f);
                            shz[(r0 + 8) * HPITCH + c0 + 1] = fmaxf(d[3] + b1, 0.0f);
                        }
                }
                __syncthreads();
                // split scan: 4 threads/row, 32 cols each
                {
                    int r = tid >> 2, q = tid & 3;
                    float run = 0.0f;
                    float4* rp = (float4*)(shz + r * HPITCH + q * 32);
#pragma unroll
                    for (int j = 0; j < 8; j++) {
                        float4 v4 = rp[j];
                        v4.x += run; v4.y += v4.x; v4.z += v4.y; v4.w += v4.z;
                        run = v4.w;
                        rp[j] = v4;
                    }
                    stot[q * 128 + r] = run;
                }
                __syncthreads();
                // prefix per (row, quarter); q==3 thread also updates carry
                {
                    int r = tid >> 2, q = tid & 3;
                    float p = scarry[r];
                    if (q > 0) p += stot[0 * 128 + r];
                    if (q > 1) p += stot[1 * 128 + r];
                    if (q > 2) p += stot[2 * 128 + r];
                    spref[r * 4 + q] = p;
                    if (q == 3) scarry[r] = p + stot[3 * 128 + r];
                }
                __syncthreads();
                // coalesced store
#pragma unroll
                for (int it = 0; it < 8; it++) {
                    int idx = it * 512 + tid;          // 4096 float4
                    int row = idx >> 5;
                    int c4 = (idx & 31) * 4;
                    float add = spref[row * 4 + (c4 >> 5)];
                    const float* rp = shz + row * HPITCH + c4;
                    float4 o = { rp[0] + add, rp[1] + add, rp[2] + add, rp[3] + add };
                    *(float4*)(out + (size_t)(bm + row) * T_DIM + nc * BN + half * 128 + c4) = o;
                }
            }
            if (nc == 0) {
#pragma unroll
                for (int j = 0; j < 64; j++) acc[j] = 0.0f;
            }
        }
    }
}

extern "C" void kernel_launch(void* const* d_in, const int* in_sizes, int n_in,
                              void* d_out, int out_size) {
    const float* x  = (const float*)d_in[0];
    const float* Wh = (const float*)d_in[1];
    const float* bh = (const float*)d_in[2];
    const float* Wb = (const float*)d_in[3];
    const float* bb = (const float*)d_in[4];
    float* out = (float*)d_out;

    const int B = in_sizes[0] / D_DIM;   // 16384

    cudaFuncSetAttribute(fused_kernel,
                         cudaFuncAttributeMaxDynamicSharedMemorySize, SMEM_TOTAL);

    wh_conv_kernel<<<(T_DIM * D_DIM) / 1024, 256>>>(Wh);
    x_conv_base_kernel<<<B, 256>>>(x, Wb, bb);
    fused_kernel<<<B / BM, THREADS, SMEM_TOTAL>>>(bh, out);
}

// round 10
// speedup vs baseline: 1.2536x; 1.0231x over previous
#include <cuda_runtime.h>
#include <cuda_fp16.h>
#include <cstdint>

// Problem: B=16384, D=1024, T=512
// out[b,t] = (x@Wb + bb) + cumsum_t( relu(x@Wh^T + bh) )
// FP16 HMMA, 512 threads / 16 warps, warp tile 32x64. BK=64 (32 mainloop
// iters, half the per-iter sync overhead of r8). A path: direct LDG fp32 ->
// in-register convert -> per-group conv buffer (named barrier), killing the
// x_conv prologue and its 96MB round trip. B via 4-stage cp.async.

#define D_DIM 1024
#define T_DIM 512
#define BM    128
#define BN    256
#define BK    64
#define THREADS 512
#define HPITCH 68             // floats, per 64-col quarter

// ---- global scratch ----
__device__ __half g_wh[T_DIM * D_DIM];

// ---- smem layout (bytes) ----
#define SM_BH    0                       // 512 f (2048)
#define SM_WB    2048                    // 1024 f (4096)
#define SM_CARRY 6144                    // 128 f (512)
#define SM_STOT0 6656                    // 128 f (512)
#define SM_STOT1 7168                    // 128 f (512)
#define SM_RED   7680                    // 512 f (2048)
#define SM_CONV  9728                    // 4 groups x 2 x 4096 = 32768
#define SM_BSTG  42496                   // 4 stages x 32768 = 131072
#define SM_HAZ   173568                  // 128*68*4 = 34816
#define SMEM_TOTAL 208384

// ---------------- helpers ----------------
__device__ __forceinline__ uint32_t smem_u32(const void* p) {
    uint32_t a;
    asm("{ .reg .u64 t; cvta.to.shared.u64 t, %1; cvt.u32.u64 %0, t; }" : "=r"(a) : "l"(p));
    return a;
}
__device__ __forceinline__ uint32_t swz128(uint32_t o) { return o ^ ((o >> 3) & 0x70); }

#define CP16(dst, src) \
    asm volatile("cp.async.cg.shared.global [%0], [%1], 16;" :: "r"(dst), "l"(src) : "memory")
#define CP_COMMIT() asm volatile("cp.async.commit_group;" ::: "memory")
#define CP_WAIT0()  asm volatile("cp.async.wait_group 0;" ::: "memory")
#define CP_WAIT1()  asm volatile("cp.async.wait_group 1;" ::: "memory")
#define CP_WAIT2()  asm volatile("cp.async.wait_group 2;" ::: "memory")
#define GROUP_BAR(id) \
    asm volatile("bar.sync %0, 128;" :: "r"(id) : "memory")

__device__ __forceinline__ void ldsm4(uint32_t* r, uint32_t addr) {
    asm volatile("ldmatrix.sync.aligned.m8n8.x4.shared.b16 {%0,%1,%2,%3}, [%4];"
                 : "=r"(r[0]), "=r"(r[1]), "=r"(r[2]), "=r"(r[3]) : "r"(addr));
}
__device__ __forceinline__ void mma16816(float* d, const uint32_t* a, const uint32_t* b) {
    asm volatile(
        "mma.sync.aligned.m16n8k16.row.col.f32.f16.f16.f32 "
        "{%0,%1,%2,%3}, {%4,%5,%6,%7}, {%8,%9}, {%0,%1,%2,%3};"
        : "+f"(d[0]), "+f"(d[1]), "+f"(d[2]), "+f"(d[3])
        : "r"(a[0]), "r"(a[1]), "r"(a[2]), "r"(a[3]), "r"(b[0]), "r"(b[1]));
}
__device__ __forceinline__ uint32_t pk2h(float a, float b) {
    __half2 h = __floats2half2_rn(a, b);
    return *(uint32_t*)&h;
}

// -------- prologue: convert Wh to fp16 --------
__global__ __launch_bounds__(256)
void wh_conv_kernel(const float* __restrict__ Wh) {
    int i = (blockIdx.x * 256 + threadIdx.x) * 4;
    float4 w = *(const float4*)(Wh + i);
    uint2 v = { pk2h(w.x, w.y), pk2h(w.z, w.w) };
    *(uint2*)((char*)g_wh + (size_t)i * 2) = v;
}

// -------- main fused kernel --------
__global__ __launch_bounds__(THREADS, 1)
void fused_kernel(const float* __restrict__ X,
                  const float* __restrict__ bh,
                  const float* __restrict__ Wb,
                  const float* __restrict__ bb,
                  float* __restrict__ out) {
    extern __shared__ char sm[];
    const uint32_t su = smem_u32(sm);
    const int tid = threadIdx.x;
    const int lane = tid & 31;
    const int wid = tid >> 5;
    const int warprow = wid >> 2;   // group g: 0..3 -> m *32
    const int warpcol = wid & 3;    // 0..3 -> n *64
    const int bm = blockIdx.x * BM;

    float* sbh = (float*)(sm + SM_BH);
    float* swb = (float*)(sm + SM_WB);
    float* scarry = (float*)(sm + SM_CARRY);
    float* stot0 = (float*)(sm + SM_STOT0);
    float* stot1 = (float*)(sm + SM_STOT1);
    float* sred = (float*)(sm + SM_RED);
    float* shz = (float*)(sm + SM_HAZ);       // [128][HPITCH]

    for (int i = tid; i < T_DIM; i += THREADS) sbh[i] = bh[i];
    for (int i = tid; i < D_DIM; i += THREADS) swb[i] = Wb[i];
    const float bbv = bb[0];
    __syncthreads();

    // ---- conversion mapping: group g owns A rows 32g..32g+31 ----
    const int g = warprow;
    const int gt = tid & 127;
    const int cr = gt >> 2;          // row in group (0..31)
    const int cq = gt & 3;           // 16-col quarter of the 64-col chunk
    const float* xrow = X + (size_t)(bm + 32 * g + cr) * D_DIM + cq * 16;
    // conv STS destinations (swizzle xor = (cr&7)<<4 on 16B units)
    const uint32_t cdst0 = (uint32_t)cr * 128 + (((uint32_t)(2 * cq) << 4) ^ (((uint32_t)cr & 7) << 4));
    const uint32_t convg = su + SM_CONV + g * 8192;

    // ---- ldsm fragment address components (128B rows, SW128) ----
    const uint32_t xmask = ((uint32_t)lane & 7) << 4;
    const uint32_t a_rowoff = ((uint32_t)lane & 15) * 128;
    const uint32_t a_l16 = (((uint32_t)lane >> 4) & 1) * 16;
    const uint32_t b_rowoff = ((uint32_t)(warpcol * 64 + (lane & 7) + ((lane >> 4) & 1) * 8)) * 128;
    const uint32_t b_l16 = (((uint32_t)lane >> 3) & 1) * 16;

    // ---- B cp.async mapping: 2048 segs, 4/thread ----
    const int bseg = tid * 4;

    float v[16];
    float pbase = 0.0f;
    float acc[64];
#pragma unroll
    for (int j = 0; j < 64; j++) acc[j] = 0.0f;

#pragma unroll 1
    for (int i = 0; i < 34; i++) {
        // ---- issue B loads for chunk i into stage i%4 ----
        if (i < 32) {
            const int nci = i >> 4;
            const int k0 = (i & 15) * BK;
            const uint32_t sB = su + SM_BSTG + (i & 3) * 32768;
#pragma unroll
            for (int q = 0; q < 4; q++) {
                int seg = bseg + q;
                int row = seg >> 3, cu = seg & 7;
                size_t gb = ((size_t)(nci * BN + row) * D_DIM + k0) * 2 + cu * 16;
                CP16(sB + swz128((uint32_t)(row * 128 + cu * 16)), (const char*)g_wh + gb);
            }
            CP_COMMIT();
        }

        const int c = i - 2;
        if (i >= 2) {
            if (i < 32) CP_WAIT2();
            else if (i == 32) CP_WAIT1();
            else CP_WAIT0();
            __syncthreads();

            // ---- convert A chunk c (fp32 regs -> fp16 conv buffer) ----
            {
                if (c < 16) {
                    const float* wbp = swb + c * BK + cq * 16;
#pragma unroll
                    for (int j = 0; j < 16; j++) pbase = fmaf(v[j], wbp[j], pbase);
                }
                uint4 h0 = { pk2h(v[0], v[1]),  pk2h(v[2], v[3]),
                             pk2h(v[4], v[5]),  pk2h(v[6], v[7]) };
                uint4 h1 = { pk2h(v[8], v[9]),  pk2h(v[10], v[11]),
                             pk2h(v[12], v[13]), pk2h(v[14], v[15]) };
                uint32_t cb = convg + (c & 1) * 4096;
                *(uint4*)(sm + (cb - su) + cdst0)        = h0;
                *(uint4*)(sm + (cb - su) + (cdst0 ^ 16)) = h1;
            }
        }

        // ---- LDG A fp32 for chunk i-1 (consumed next iteration) ----
        if (i >= 1 && i < 33) {
            const int ci = i - 1;
            const float* xp = xrow + (ci & 15) * BK;
            *(float4*)(v + 0)  = *(const float4*)(xp + 0);
            *(float4*)(v + 4)  = *(const float4*)(xp + 4);
            *(float4*)(v + 8)  = *(const float4*)(xp + 8);
            *(float4*)(v + 12) = *(const float4*)(xp + 12);
        }

        if (i < 2) continue;

        GROUP_BAR(g + 1);

        // ---- compute chunk c ----
        {
            const uint32_t aB = convg + (c & 1) * 4096;
            const uint32_t sB = su + SM_BSTG + (c & 3) * 32768;
#pragma unroll
            for (int kk = 0; kk < 4; kk++) {
                const uint32_t akb = ((uint32_t)kk * 32 + a_l16) ^ xmask;
                const uint32_t bkb = ((uint32_t)kk * 32 + b_l16) ^ xmask;
                uint32_t bfr[4][4];
#pragma unroll
                for (int p = 0; p < 4; p++)
                    ldsm4(bfr[p], sB + b_rowoff + p * 2048 + bkb);
#pragma unroll
                for (int mt = 0; mt < 2; mt++) {
                    uint32_t af[4];
                    ldsm4(af, aB + a_rowoff + mt * 2048 + akb);
#pragma unroll
                    for (int nt = 0; nt < 8; nt++) {
                        float* d = acc + (mt * 8 + nt) * 4;
                        mma16816(d, af, &bfr[nt >> 1][(nt & 1) * 2]);
                    }
                }
            }
        }

        // ---- nc boundary: epilogue ----
        if (c == 15 || c == 31) {
            const int nc = c >> 4;
            if (nc == 0) {
                // base reduction -> carry init
                __syncthreads();
                sred[tid] = pbase;
                __syncthreads();
                if (tid < BM) {
                    int o = (tid >> 5) * 128 + (tid & 31) * 4;
                    scarry[tid] = sred[o] + sred[o + 1] + sred[o + 2] + sred[o + 3] + bbv;
                }
            }
#pragma unroll 1
            for (int quarter = 0; quarter < 4; quarter++) {
                __syncthreads();
                // warps whose 64 n-cols == this quarter write hazards
                if (warpcol == quarter) {
#pragma unroll
                    for (int mt = 0; mt < 2; mt++)
#pragma unroll
                        for (int nt = 0; nt < 8; nt++) {
                            const float* d = acc + (mt * 8 + nt) * 4;
                            int r0 = warprow * 32 + mt * 16 + (lane >> 2);
                            int c0 = nt * 8 + 2 * (lane & 3);
                            int cg = nc * BN + quarter * 64 + c0;
                            float b0 = sbh[cg], b1 = sbh[cg + 1];
                            shz[r0 * HPITCH + c0]           = fmaxf(d[0] + b0, 0.0f);
                            shz[r0 * HPITCH + c0 + 1]       = fmaxf(d[1] + b1, 0.0f);
                            shz[(r0 + 8) * HPITCH + c0]     = fmaxf(d[2] + b0, 0.0f);
                            shz[(r0 + 8) * HPITCH + c0 + 1] = fmaxf(d[3] + b1, 0.0f);
                        }
                }
                __syncthreads();
                // split scan: 2 threads/row, 32 cols each
                if (tid < 256) {
                    int r = tid >> 1, hh = tid & 1;
                    float run = 0.0f;
                    float4* rp = (float4*)(shz + r * HPITCH + hh * 32);
#pragma unroll
                    for (int j = 0; j < 8; j++) {
                        float4 v4 = rp[j];
                        v4.x += run; v4.y += v4.x; v4.z += v4.y; v4.w += v4.z;
                        run = v4.w;
                        rp[j] = v4;
                    }
                    if (hh == 0) stot0[r] = run; else stot1[r] = run;
                }
                __syncthreads();
                // coalesced store (+carry, +half fixup)
#pragma unroll
                for (int it = 0; it < 4; it++) {
                    int idx = it * 512 + tid;          // 2048 float4
                    int row = idx >> 4;
                    int c4 = (idx & 15) * 4;
                    float add = scarry[row] + ((c4 & 32) ? stot0[row] : 0.0f);
                    const float* rp = shz + row * HPITCH + c4;
                    float4 o = { rp[0] + add, rp[1] + add, rp[2] + add, rp[3] + add };
                    *(float4*)(out + (size_t)(bm + row) * T_DIM + nc * BN + quarter * 64 + c4) = o;
                }
                __syncthreads();
                if (tid < BM) scarry[tid] += stot0[tid] + stot1[tid];
            }
            if (nc == 0) {
#pragma unroll
                for (int j = 0; j < 64; j++) acc[j] = 0.0f;
            }
        }
    }
}

extern "C" void kernel_launch(void* const* d_in, const int* in_sizes, int n_in,
                              void* d_out, int out_size) {
    const float* x  = (const float*)d_in[0];
    const float* Wh = (const float*)d_in[1];
    const float* bh = (const float*)d_in[2];
    const float* Wb = (const float*)d_in[3];
    const float* bb = (const float*)d_in[4];
    float* out = (float*)d_out;

    const int B = in_sizes[0] / D_DIM;   // 16384

    cudaFuncSetAttribute(fused_kernel,
                         cudaFuncAttributeMaxDynamicSharedMemorySize, SMEM_TOTAL);

    wh_conv_kernel<<<(T_DIM * D_DIM) / 1024, 256>>>(Wh);
    fused_kernel<<<B / BM, THREADS, SMEM_TOTAL>>>(x, bh, Wb, bb, out);
}

// round 11
// speedup vs baseline: 1.4072x; 1.1225x over previous
#include <cuda_runtime.h>
#include <cuda_fp16.h>
#include <cstdint>

// Problem: B=16384, D=1024, T=512
// out[b,t] = (x@Wb + bb) + cumsum_t( relu(x@Wh^T + bh) )
// FP16 HMMA, 512 threads / 16 warps, warp tile 32x64, BK=64 (32 iters).
// A path: LDG fp32 -> in-register convert, SOFTWARE-PIPELINED one chunk ahead
// and interleaved between the MMA kk-blocks (r10 serialized it -> +18us).
// B via 4-stage cp.async. Fused carry-scan epilogue.

#define D_DIM 1024
#define T_DIM 512
#define BM    128
#define BN    256
#define BK    64
#define THREADS 512
#define HPITCH 68             // floats, per 64-col quarter

// ---- global scratch ----
__device__ __half g_wh[T_DIM * D_DIM];

// ---- smem layout (bytes) ----
#define SM_BH    0                       // 512 f (2048)
#define SM_WB    2048                    // 1024 f (4096)
#define SM_CARRY 6144                    // 128 f (512)
#define SM_STOT0 6656                    // 128 f (512)
#define SM_STOT1 7168                    // 128 f (512)
#define SM_RED   7680                    // 512 f (2048)
#define SM_CONV  9728                    // 4 groups x 2 x 4096 = 32768
#define SM_BSTG  42496                   // 4 stages x 32768 = 131072
#define SM_HAZ   173568                  // 128*68*4 = 34816
#define SMEM_TOTAL 208384

// ---------------- helpers ----------------
__device__ __forceinline__ uint32_t smem_u32(const void* p) {
    uint32_t a;
    asm("{ .reg .u64 t; cvta.to.shared.u64 t, %1; cvt.u32.u64 %0, t; }" : "=r"(a) : "l"(p));
    return a;
}
__device__ __forceinline__ uint32_t swz128(uint32_t o) { return o ^ ((o >> 3) & 0x70); }

#define CP16(dst, src) \
    asm volatile("cp.async.cg.shared.global [%0], [%1], 16;" :: "r"(dst), "l"(src) : "memory")
#define CP_COMMIT() asm volatile("cp.async.commit_group;" ::: "memory")
#define CP_WAIT0()  asm volatile("cp.async.wait_group 0;" ::: "memory")
#define CP_WAIT1()  asm volatile("cp.async.wait_group 1;" ::: "memory")
#define CP_WAIT2()  asm volatile("cp.async.wait_group 2;" ::: "memory")
#define GROUP_BAR(id) \
    asm volatile("bar.sync %0, 128;" :: "r"(id) : "memory")

__device__ __forceinline__ void ldsm4(uint32_t* r, uint32_t addr) {
    asm volatile("ldmatrix.sync.aligned.m8n8.x4.shared.b16 {%0,%1,%2,%3}, [%4];"
                 : "=r"(r[0]), "=r"(r[1]), "=r"(r[2]), "=r"(r[3]) : "r"(addr));
}
__device__ __forceinline__ void mma16816(float* d, const uint32_t* a, const uint32_t* b) {
    asm volatile(
        "mma.sync.aligned.m16n8k16.row.col.f32.f16.f16.f32 "
        "{%0,%1,%2,%3}, {%4,%5,%6,%7}, {%8,%9}, {%0,%1,%2,%3};"
        : "+f"(d[0]), "+f"(d[1]), "+f"(d[2]), "+f"(d[3])
        : "r"(a[0]), "r"(a[1]), "r"(a[2]), "r"(a[3]), "r"(b[0]), "r"(b[1]));
}
__device__ __forceinline__ uint32_t pk2h(float a, float b) {
    __half2 h = __floats2half2_rn(a, b);
    return *(uint32_t*)&h;
}

// -------- prologue: convert Wh to fp16 --------
__global__ __launch_bounds__(256)
void wh_conv_kernel(const float* __restrict__ Wh) {
    int i = (blockIdx.x * 256 + threadIdx.x) * 4;
    float4 w = *(const float4*)(Wh + i);
    uint2 v = { pk2h(w.x, w.y), pk2h(w.z, w.w) };
    *(uint2*)((char*)g_wh + (size_t)i * 2) = v;
}

// -------- main fused kernel --------
__global__ __launch_bounds__(THREADS, 1)
void fused_kernel(const float* __restrict__ X,
                  const float* __restrict__ bh,
                  const float* __restrict__ Wb,
                  const float* __restrict__ bb,
                  float* __restrict__ out) {
    extern __shared__ char sm[];
    const uint32_t su = smem_u32(sm);
    const int tid = threadIdx.x;
    const int lane = tid & 31;
    const int wid = tid >> 5;
    const int warprow = wid >> 2;   // group g: 0..3 -> m *32
    const int warpcol = wid & 3;    // 0..3 -> n *64
    const int bm = blockIdx.x * BM;

    float* sbh = (float*)(sm + SM_BH);
    float* swb = (float*)(sm + SM_WB);
    float* scarry = (float*)(sm + SM_CARRY);
    float* stot0 = (float*)(sm + SM_STOT0);
    float* stot1 = (float*)(sm + SM_STOT1);
    float* sred = (float*)(sm + SM_RED);
    float* shz = (float*)(sm + SM_HAZ);       // [128][HPITCH]

    for (int i = tid; i < T_DIM; i += THREADS) sbh[i] = bh[i];
    for (int i = tid; i < D_DIM; i += THREADS) swb[i] = Wb[i];
    const float bbv = bb[0];
    __syncthreads();

    // ---- conversion mapping: group g owns A rows 32g..32g+31 ----
    const int g = warprow;
    const int gt = tid & 127;
    const int cr = gt >> 2;          // row in group (0..31)
    const int cq = gt & 3;           // 16-col quarter of the 64-col chunk
    const float* xrow = X + (size_t)(bm + 32 * g + cr) * D_DIM + cq * 16;
    const uint32_t cdst0 = (uint32_t)cr * 128 + (((uint32_t)(2 * cq) << 4) ^ (((uint32_t)cr & 7) << 4));
    const uint32_t convoff = SM_CONV + g * 8192;

    // ---- ldsm fragment address components (128B rows, SW128) ----
    const uint32_t xmask = ((uint32_t)lane & 7) << 4;
    const uint32_t a_rowoff = ((uint32_t)lane & 15) * 128;
    const uint32_t a_l16 = (((uint32_t)lane >> 4) & 1) * 16;
    const uint32_t b_rowoff = ((uint32_t)(warpcol * 64 + (lane & 7) + ((lane >> 4) & 1) * 8)) * 128;
    const uint32_t b_l16 = (((uint32_t)lane >> 3) & 1) * 16;

    // ---- B cp.async mapping: 2048 segs, 4/thread ----
    const int bseg = tid * 4;

    float v[16];
    float pbase = 0.0f;
    float acc[64];
#pragma unroll
    for (int j = 0; j < 64; j++) acc[j] = 0.0f;

    // one kk compute block
    #define COMPUTE_KK(kk)                                                     \
    {                                                                          \
        const uint32_t akb = ((uint32_t)(kk) * 32 + a_l16) ^ xmask;            \
        const uint32_t bkb = ((uint32_t)(kk) * 32 + b_l16) ^ xmask;            \
        uint32_t bfr[4][4];                                                    \
        _Pragma("unroll")                                                      \
        for (int p = 0; p < 4; p++)                                            \
            ldsm4(bfr[p], sB + b_rowoff + p * 2048 + bkb);                     \
        _Pragma("unroll")                                                      \
        for (int mt = 0; mt < 2; mt++) {                                       \
            uint32_t af[4];                                                    \
            ldsm4(af, aB + a_rowoff + mt * 2048 + akb);                        \
            _Pragma("unroll")                                                  \
            for (int nt = 0; nt < 8; nt++) {                                   \
                float* d = acc + (mt * 8 + nt) * 4;                            \
                mma16816(d, af, &bfr[nt >> 1][(nt & 1) * 2]);                  \
            }                                                                  \
        }                                                                      \
    }

    // ---- prologue iters 0..1 ----
    {
        // iter 0: issue B0, LDG chunk0
        {
            const uint32_t sB = su + SM_BSTG + 0 * 32768;
#pragma unroll
            for (int q = 0; q < 4; q++) {
                int seg = bseg + q;
                int row = seg >> 3, cu = seg & 7;
                size_t gb = ((size_t)row * D_DIM + 0) * 2 + cu * 16;
                CP16(sB + swz128((uint32_t)(row * 128 + cu * 16)), (const char*)g_wh + gb);
            }
            CP_COMMIT();
            *(float4*)(v + 0)  = *(const float4*)(xrow + 0);
            *(float4*)(v + 4)  = *(const float4*)(xrow + 4);
            *(float4*)(v + 8)  = *(const float4*)(xrow + 8);
            *(float4*)(v + 12) = *(const float4*)(xrow + 12);
        }
        // iter 1: issue B1, convert chunk0 -> buf0 (+pbase), LDG chunk1, bar
        {
            const uint32_t sB = su + SM_BSTG + 1 * 32768;
#pragma unroll
            for (int q = 0; q < 4; q++) {
                int seg = bseg + q;
                int row = seg >> 3, cu = seg & 7;
                size_t gb = ((size_t)row * D_DIM + BK) * 2 + cu * 16;
                CP16(sB + swz128((uint32_t)(row * 128 + cu * 16)), (const char*)g_wh + gb);
            }
            CP_COMMIT();
            const float* wbp = swb + cq * 16;
#pragma unroll
            for (int j = 0; j < 16; j++) pbase = fmaf(v[j], wbp[j], pbase);
            uint4 h0 = { pk2h(v[0], v[1]),  pk2h(v[2], v[3]),
                         pk2h(v[4], v[5]),  pk2h(v[6], v[7]) };
            uint4 h1 = { pk2h(v[8], v[9]),  pk2h(v[10], v[11]),
                         pk2h(v[12], v[13]), pk2h(v[14], v[15]) };
            *(uint4*)(sm + convoff + cdst0)        = h0;
            *(uint4*)(sm + convoff + (cdst0 ^ 16)) = h1;
            const float* xp = xrow + BK;
            *(float4*)(v + 0)  = *(const float4*)(xp + 0);
            *(float4*)(v + 4)  = *(const float4*)(xp + 4);
            *(float4*)(v + 8)  = *(const float4*)(xp + 8);
            *(float4*)(v + 12) = *(const float4*)(xp + 12);
            GROUP_BAR(g + 1);
        }
    }

    // ---- main loop: iters 2..33, compute chunk c=i-2 ----
#pragma unroll 1
    for (int i = 2; i < 34; i++) {
        // issue B loads for chunk i into stage i%4
        if (i < 32) {
            const int nci = i >> 4;
            const int k0 = (i & 15) * BK;
            const uint32_t sB = su + SM_BSTG + (i & 3) * 32768;
#pragma unroll
            for (int q = 0; q < 4; q++) {
                int seg = bseg + q;
                int row = seg >> 3, cu = seg & 7;
                size_t gb = ((size_t)(nci * BN + row) * D_DIM + k0) * 2 + cu * 16;
                CP16(sB + swz128((uint32_t)(row * 128 + cu * 16)), (const char*)g_wh + gb);
            }
            CP_COMMIT();
        }

        const int c = i - 2;
        const int cc = c + 1;                 // chunk being converted
        if (i < 32) CP_WAIT2();
        else if (i == 32) CP_WAIT1();
        else CP_WAIT0();
        __syncthreads();

        const uint32_t aB = su + convoff - SM_CONV + SM_CONV + (c & 1) * 4096 + g * 0; // see below
        const uint32_t aB2 = su + SM_CONV + g * 8192 + (c & 1) * 4096;
        const uint32_t sB = su + SM_BSTG + (c & 3) * 32768;
        (void)aB;

        {
            const uint32_t aB = aB2;
            const bool docv = (cc < 32);
            const bool dobase = (cc < 16);

            COMPUTE_KK(0)
            if (docv) {
                if (dobase) {
                    const float* wbp = swb + cc * BK + cq * 16;
#pragma unroll
                    for (int j = 0; j < 8; j++) pbase = fmaf(v[j], wbp[j], pbase);
                }
                uint4 h0 = { pk2h(v[0], v[1]), pk2h(v[2], v[3]),
                             pk2h(v[4], v[5]), pk2h(v[6], v[7]) };
                *(uint4*)(sm + SM_CONV + g * 8192 + (cc & 1) * 4096 + cdst0) = h0;
            }
            COMPUTE_KK(1)
            if (docv) {
                if (dobase) {
                    const float* wbp = swb + cc * BK + cq * 16;
#pragma unroll
                    for (int j = 8; j < 16; j++) pbase = fmaf(v[j], wbp[j], pbase);
                }
                uint4 h1 = { pk2h(v[8], v[9]),  pk2h(v[10], v[11]),
                             pk2h(v[12], v[13]), pk2h(v[14], v[15]) };
                *(uint4*)(sm + SM_CONV + g * 8192 + (cc & 1) * 4096 + (cdst0 ^ 16)) = h1;
            }
            COMPUTE_KK(2)
            if (i < 32) {
                const float* xp = xrow + (i & 15) * BK;
                *(float4*)(v + 0)  = *(const float4*)(xp + 0);
                *(float4*)(v + 4)  = *(const float4*)(xp + 4);
                *(float4*)(v + 8)  = *(const float4*)(xp + 8);
                *(float4*)(v + 12) = *(const float4*)(xp + 12);
            }
            COMPUTE_KK(3)
        }

        GROUP_BAR(g + 1);

        // ---- nc boundary: epilogue ----
        if (c == 15 || c == 31) {
            const int nc = c >> 4;
            if (nc == 0) {
                __syncthreads();
                sred[tid] = pbase;
                __syncthreads();
                if (tid < BM) {
                    int o = (tid >> 5) * 128 + (tid & 31) * 4;
                    scarry[tid] = sred[o] + sred[o + 1] + sred[o + 2] + sred[o + 3] + bbv;
                }
            }
#pragma unroll 1
            for (int quarter = 0; quarter < 4; quarter++) {
                __syncthreads();
                if (warpcol == quarter) {
#pragma unroll
                    for (int mt = 0; mt < 2; mt++)
#pragma unroll
                        for (int nt = 0; nt < 8; nt++) {
                            const float* d = acc + (mt * 8 + nt) * 4;
                            int r0 = warprow * 32 + mt * 16 + (lane >> 2);
                            int c0 = nt * 8 + 2 * (lane & 3);
                            int cg = nc * BN + quarter * 64 + c0;
                            float b0 = sbh[cg], b1 = sbh[cg + 1];
                            shz[r0 * HPITCH + c0]           = fmaxf(d[0] + b0, 0.0f);
                            shz[r0 * HPITCH + c0 + 1]       = fmaxf(d[1] + b1, 0.0f);
                            shz[(r0 + 8) * HPITCH + c0]     = fmaxf(d[2] + b0, 0.0f);
                            shz[(r0 + 8) * HPITCH + c0 + 1] = fmaxf(d[3] + b1, 0.0f);
                        }
                }
                __syncthreads();
                if (tid < 256) {
                    int r = tid >> 1, hh = tid & 1;
                    float run = 0.0f;
                    float4* rp = (float4*)(shz + r * HPITCH + hh * 32);
#pragma unroll
                    for (int j = 0; j < 8; j++) {
                        float4 v4 = rp[j];
                        v4.x += run; v4.y += v4.x; v4.z += v4.y; v4.w += v4.z;
                        run = v4.w;
                        rp[j] = v4;
                    }
                    if (hh == 0) stot0[r] = run; else stot1[r] = run;
                }
                __syncthreads();
#pragma unroll
                for (int it = 0; it < 4; it++) {
                    int idx = it * 512 + tid;          // 2048 float4
                    int row = idx >> 4;
                    int c4 = (idx & 15) * 4;
                    float add = scarry[row] + ((c4 & 32) ? stot0[row] : 0.0f);
                    const float* rp = shz + row * HPITCH + c4;
                    float4 o = { rp[0] + add, rp[1] + add, rp[2] + add, rp[3] + add };
                    *(float4*)(out + (size_t)(bm + row) * T_DIM + nc * BN + quarter * 64 + c4) = o;
                }
                __syncthreads();
                if (tid < BM) scarry[tid] += stot0[tid] + stot1[tid];
            }
            if (nc == 0) {
#pragma unroll
                for (int j = 0; j < 64; j++) acc[j] = 0.0f;
            }
        }
    }
    #undef COMPUTE_KK
}

extern "C" void kernel_launch(void* const* d_in, const int* in_sizes, int n_in,
                              void* d_out, int out_size) {
    const float* x  = (const float*)d_in[0];
    const float* Wh = (const float*)d_in[1];
    const float* bh = (const float*)d_in[2];
    const float* Wb = (const float*)d_in[3];
    const float* bb = (const float*)d_in[4];
    float* out = (float*)d_out;

    const int B = in_sizes[0] / D_DIM;   // 16384

    cudaFuncSetAttribute(fused_kernel,
                         cudaFuncAttributeMaxDynamicSharedMemorySize, SMEM_TOTAL);

    wh_conv_kernel<<<(T_DIM * D_DIM) / 1024, 256>>>(Wh);
    fused_kernel<<<B / BM, THREADS, SMEM_TOTAL>>>(x, bh, Wb, bb, out);
}